// round 2
// baseline (speedup 1.0000x reference)
#include <cuda_runtime.h>

#define Nn   50000
#define Ee   800000
#define ETe  850000      // edges + self loops
#define FIN  128
#define HD   128         // HEADS*HID
#define HID  32
#define NH   4
#define NCLS 16
#define NEG  0.2f

// ---------------- scratch (device globals; no allocation allowed) ----------
__device__ float g_h1  [(size_t)Nn * HD];     // x @ W1
__device__ float g_out1[(size_t)Nn * HD];     // layer1 aggregation
__device__ float g_als1[Nn * NH];
__device__ float g_ald1[Nn * NH];
__device__ float g_m1  [Nn * NH];
__device__ float g_den1[Nn * NH];
__device__ float g_ex1 [(size_t)ETe * NH];
__device__ float g_h2  [Nn * NCLS];           // elu(out1+b1) @ W2
__device__ float g_als2[Nn];
__device__ float g_ald2[Nn];
__device__ float g_m2  [Nn];
__device__ float g_den2[Nn];
__device__ float g_ex2 [ETe];
__device__ float g_out2[Nn * NCLS];

__device__ __forceinline__ float negInf() { return __int_as_float(0xff800000); }

// float atomic max: int-max for >=0, uint-min for <0 (init must be -inf)
__device__ __forceinline__ void atomicMaxF(float* addr, float v) {
    if (v >= 0.f) atomicMax((int*)addr, __float_as_int(v));
    else          atomicMin((unsigned int*)addr, __float_as_uint(v));
}

// ---------------- init ------------------------------------------------------
__global__ void k_init() {
    int i = blockIdx.x * blockDim.x + threadIdx.x;
    if (i < Nn * HD)   g_out1[i] = 0.f;
    if (i < Nn * NCLS) g_out2[i] = 0.f;
    if (i < Nn * NH) { g_m1[i] = negInf(); g_den1[i] = 0.f; }
    if (i < Nn)      { g_m2[i] = negInf(); g_den2[i] = 0.f; }
}

// ---------------- GEMM1: g_h1 = x @ W1  (N x 128 @ 128 x 128) --------------
__global__ void k_gemm1(const float* __restrict__ x, const float* __restrict__ W) {
    __shared__ float xs[32][33];
    __shared__ __align__(16) float Ws[32 * 128];

    int tid = threadIdx.x;        // 256 threads
    int ty = tid >> 5;            // 0..7  -> 4 rows each
    int tx = tid & 31;            // 0..31 -> 4 cols each
    int r0 = ty * 4, c0 = tx * 4;
    int rowBase = blockIdx.x * 32;

    float4 acc[4];
#pragma unroll
    for (int i = 0; i < 4; i++) acc[i] = make_float4(0.f, 0.f, 0.f, 0.f);

    int lr = tid >> 3;            // load row 0..31
    int lk = (tid & 7) * 4;       // k offset within chunk

    for (int kk = 0; kk < FIN; kk += 32) {
        // x tile [32 x 32]
        {
            int gr = rowBase + lr;
            float4 v = make_float4(0.f, 0.f, 0.f, 0.f);
            if (gr < Nn) v = *(const float4*)(x + (size_t)gr * FIN + kk + lk);
            xs[lr][lk + 0] = v.x; xs[lr][lk + 1] = v.y;
            xs[lr][lk + 2] = v.z; xs[lr][lk + 3] = v.w;
        }
        // W chunk [32 x 128] — contiguous 4096 floats
#pragma unroll
        for (int it = 0; it < 4; it++) {
            int f = it * 1024 + tid * 4;
            *(float4*)&Ws[f] = *(const float4*)(W + kk * HD + f);
        }
        __syncthreads();
#pragma unroll
        for (int k = 0; k < 32; k++) {
            float4 b = *(float4*)&Ws[k * HD + c0];
#pragma unroll
            for (int i = 0; i < 4; i++) {
                float a = xs[r0 + i][k];
                acc[i].x += a * b.x; acc[i].y += a * b.y;
                acc[i].z += a * b.z; acc[i].w += a * b.w;
            }
        }
        __syncthreads();
    }
#pragma unroll
    for (int i = 0; i < 4; i++) {
        int gr = rowBase + r0 + i;
        if (gr < Nn) *(float4*)(g_h1 + (size_t)gr * HD + c0) = acc[i];
    }
}

// ---------------- per-node attention logits, layer 1 ------------------------
__global__ void k_attn1(const float* __restrict__ a_src, const float* __restrict__ a_dst) {
    __shared__ float s_as[NH * HID], s_ad[NH * HID];
    if (threadIdx.x < NH * HID) {
        s_as[threadIdx.x] = a_src[threadIdx.x];
        s_ad[threadIdx.x] = a_dst[threadIdx.x];
    }
    __syncthreads();
    int i = blockIdx.x * blockDim.x + threadIdx.x;   // i = n*NH + h
    if (i >= Nn * NH) return;
    int n = i >> 2, h = i & 3;
    const float* hp = g_h1 + (size_t)n * HD + h * HID;
    float ss = 0.f, sd = 0.f;
#pragma unroll
    for (int d = 0; d < HID; d++) {
        float v = hp[d];
        ss += v * s_as[h * HID + d];
        sd += v * s_ad[h * HID + d];
    }
    g_als1[i] = ss; g_ald1[i] = sd;
}

// ---------------- layer1 edge passes ---------------------------------------
__global__ void k_emax1(const int* __restrict__ src, const int* __restrict__ dst) {
    int e = blockIdx.x * blockDim.x + threadIdx.x;
    if (e >= ETe) return;
    int s = (e < Ee) ? src[e] : e - Ee;
    int d = (e < Ee) ? dst[e] : e - Ee;
    float4 as = *(const float4*)(g_als1 + s * NH);
    float4 ad = *(const float4*)(g_ald1 + d * NH);
    float v[4] = { as.x + ad.x, as.y + ad.y, as.z + ad.z, as.w + ad.w };
#pragma unroll
    for (int h = 0; h < 4; h++) {
        float u = v[h] > 0.f ? v[h] : NEG * v[h];
        atomicMaxF(&g_m1[d * NH + h], u);
    }
}

__global__ void k_eexp1(const int* __restrict__ src, const int* __restrict__ dst) {
    int e = blockIdx.x * blockDim.x + threadIdx.x;
    if (e >= ETe) return;
    int s = (e < Ee) ? src[e] : e - Ee;
    int d = (e < Ee) ? dst[e] : e - Ee;
    float4 as = *(const float4*)(g_als1 + s * NH);
    float4 ad = *(const float4*)(g_ald1 + d * NH);
    float4 m  = *(const float4*)(g_m1   + d * NH);
    float v[4] = { as.x + ad.x, as.y + ad.y, as.z + ad.z, as.w + ad.w };
    float mm[4] = { m.x, m.y, m.z, m.w };
    float4 exv;
    float* exp_out = (float*)&exv;
#pragma unroll
    for (int h = 0; h < 4; h++) {
        float u = v[h] > 0.f ? v[h] : NEG * v[h];
        float ex = __expf(u - mm[h]);
        exp_out[h] = ex;
        atomicAdd(&g_den1[d * NH + h], ex);
    }
    *(float4*)(g_ex1 + (size_t)e * NH) = exv;
}

// warp per edge: 32 lanes x float4 = 128 features
__global__ void k_scat1(const int* __restrict__ src, const int* __restrict__ dst) {
    int gt = blockIdx.x * blockDim.x + threadIdx.x;
    int w = gt >> 5, lane = gt & 31;
    if (w >= ETe) return;
    int s = (w < Ee) ? src[w] : w - Ee;
    int d = (w < Ee) ? dst[w] : w - Ee;
    int head = lane >> 3;   // 8 lanes per head
    float alpha = g_ex1[(size_t)w * NH + head] / g_den1[d * NH + head];
    float4 v = *(const float4*)(g_h1 + (size_t)s * HD + lane * 4);
    float* o = g_out1 + (size_t)d * HD + lane * 4;
    atomicAdd(o + 0, v.x * alpha);
    atomicAdd(o + 1, v.y * alpha);
    atomicAdd(o + 2, v.z * alpha);
    atomicAdd(o + 3, v.w * alpha);
}

// ---------------- GEMM2 (fused bias+elu on input) + layer2 logits ----------
__global__ void k_gemm2(const float* __restrict__ b1, const float* __restrict__ W2,
                        const float* __restrict__ as2, const float* __restrict__ ad2) {
    __shared__ float sW[HD * NCLS];
    __shared__ float sb[HD];
    __shared__ float sa[NCLS], sdv[NCLS];
    int t = threadIdx.x;   // 128 threads
    for (int i = t; i < HD * NCLS; i += 128) sW[i] = W2[i];
    sb[t] = b1[t];
    if (t < NCLS) { sa[t] = as2[t]; sdv[t] = ad2[t]; }
    __syncthreads();
    int n = blockIdx.x * 128 + t;
    if (n >= Nn) return;
    float acc[NCLS];
#pragma unroll
    for (int c = 0; c < NCLS; c++) acc[c] = 0.f;
    const float* xp = g_out1 + (size_t)n * HD;
    for (int k = 0; k < HD; k++) {
        float xv = xp[k] + sb[k];
        xv = xv > 0.f ? xv : expm1f(xv);          // elu
#pragma unroll
        for (int c = 0; c < NCLS; c++) acc[c] += xv * sW[k * NCLS + c];
    }
    float ss = 0.f, sd = 0.f;
#pragma unroll
    for (int c = 0; c < NCLS; c++) {
        g_h2[n * NCLS + c] = acc[c];
        ss += acc[c] * sa[c];
        sd += acc[c] * sdv[c];
    }
    g_als2[n] = ss; g_ald2[n] = sd;
}

// ---------------- layer2 edge passes (1 head) -------------------------------
__global__ void k_emax2(const int* __restrict__ src, const int* __restrict__ dst) {
    int e = blockIdx.x * blockDim.x + threadIdx.x;
    if (e >= ETe) return;
    int s = (e < Ee) ? src[e] : e - Ee;
    int d = (e < Ee) ? dst[e] : e - Ee;
    float v = g_als2[s] + g_ald2[d];
    v = v > 0.f ? v : NEG * v;
    atomicMaxF(&g_m2[d], v);
}

__global__ void k_eexp2(const int* __restrict__ src, const int* __restrict__ dst) {
    int e = blockIdx.x * blockDim.x + threadIdx.x;
    if (e >= ETe) return;
    int s = (e < Ee) ? src[e] : e - Ee;
    int d = (e < Ee) ? dst[e] : e - Ee;
    float v = g_als2[s] + g_ald2[d];
    v = v > 0.f ? v : NEG * v;
    float ex = __expf(v - g_m2[d]);
    g_ex2[e] = ex;
    atomicAdd(&g_den2[d], ex);
}

// 4 threads per edge: each handles a float4 chunk of the 16 classes
__global__ void k_scat2(const int* __restrict__ src, const int* __restrict__ dst) {
    int idx = blockIdx.x * blockDim.x + threadIdx.x;
    if (idx >= ETe * 4) return;
    int e = idx >> 2, q = idx & 3;
    int s = (e < Ee) ? src[e] : e - Ee;
    int d = (e < Ee) ? dst[e] : e - Ee;
    float alpha = g_ex2[e] / g_den2[d];
    float4 v = *(const float4*)(g_h2 + s * NCLS + q * 4);
    float* o = g_out2 + d * NCLS + q * 4;
    atomicAdd(o + 0, v.x * alpha);
    atomicAdd(o + 1, v.y * alpha);
    atomicAdd(o + 2, v.z * alpha);
    atomicAdd(o + 3, v.w * alpha);
}

// ---------------- bias + log_softmax ----------------------------------------
__global__ void k_final(const float* __restrict__ b2, float* __restrict__ y) {
    __shared__ float sb[NCLS];
    if (threadIdx.x < NCLS) sb[threadIdx.x] = b2[threadIdx.x];
    __syncthreads();
    int n = blockIdx.x * blockDim.x + threadIdx.x;
    if (n >= Nn) return;
    float v[NCLS];
    float mx = negInf();
#pragma unroll
    for (int c = 0; c < NCLS; c++) {
        v[c] = g_out2[n * NCLS + c] + sb[c];
        mx = fmaxf(mx, v[c]);
    }
    float sm = 0.f;
#pragma unroll
    for (int c = 0; c < NCLS; c++) sm += __expf(v[c] - mx);
    float l = mx + logf(sm);
#pragma unroll
    for (int c = 0; c < NCLS; c++) y[n * NCLS + c] = v[c] - l;
}

// ---------------- launch -----------------------------------------------------
extern "C" void kernel_launch(void* const* d_in, const int* in_sizes, int n_in,
                              void* d_out, int out_size) {
    const float* x   = (const float*)d_in[0];
    const int*   ei  = (const int*)  d_in[1];
    const float* W1  = (const float*)d_in[2];
    const float* as1 = (const float*)d_in[3];
    const float* ad1 = (const float*)d_in[4];
    const float* b1  = (const float*)d_in[5];
    const float* W2  = (const float*)d_in[6];
    const float* as2 = (const float*)d_in[7];
    const float* ad2 = (const float*)d_in[8];
    const float* b2  = (const float*)d_in[9];
    float* out = (float*)d_out;

    const int* srcp = ei;
    const int* dstp = ei + Ee;

    k_init <<<(Nn * HD + 255) / 256, 256>>>();
    k_gemm1<<<(Nn + 31) / 32, 256>>>(x, W1);
    k_attn1<<<(Nn * NH + 255) / 256, 256>>>(as1, ad1);

    int eb = (ETe + 255) / 256;
    k_emax1<<<eb, 256>>>(srcp, dstp);
    k_eexp1<<<eb, 256>>>(srcp, dstp);
    k_scat1<<<((size_t)ETe * 32 + 255) / 256, 256>>>(srcp, dstp);

    k_gemm2<<<(Nn + 127) / 128, 128>>>(b1, W2, as2, ad2);

    k_emax2<<<eb, 256>>>(srcp, dstp);
    k_eexp2<<<eb, 256>>>(srcp, dstp);
    k_scat2<<<((size_t)ETe * 4 + 255) / 256, 256>>>(srcp, dstp);

    k_final<<<(Nn + 255) / 256, 256>>>(b2, out);
}

// round 7
// speedup vs baseline: 1.5929x; 1.5929x over previous
#include <cuda_runtime.h>

#define Nn   50000
#define Ee   800000
#define ETe  850000      // edges + self loops
#define FIN  128
#define HD   128         // HEADS*HID
#define HID  32
#define NH   4
#define NCLS 16
#define NEG  0.2f

// ---------------- scratch (device globals; no allocation allowed) ----------
__device__ float g_h1  [(size_t)Nn * HD];     // x @ W1
__device__ float g_out1[(size_t)Nn * HD];     // layer1 aggregation
__device__ float g_als1[Nn * NH];
__device__ float g_ald1[Nn * NH];
__device__ float g_h2  [Nn * NCLS];           // elu(out1+b1) @ W2
__device__ float g_als2[Nn];
__device__ float g_ald2[Nn];
__device__ float g_out2[Nn * NCLS];

// CSR by destination
__device__ int g_cnt [Nn];
__device__ int g_off [Nn + 1];
__device__ int g_cur [Nn];
__device__ int g_csrc[ETe];

__device__ __forceinline__ float negInf() { return __int_as_float(0xff800000); }
__device__ __forceinline__ float leaky(float v) { return v > 0.f ? v : NEG * v; }
__device__ __forceinline__ float sel4(float4 v, int i) {
    return i == 0 ? v.x : i == 1 ? v.y : i == 2 ? v.z : v.w;
}

// ---------------- CSR build -------------------------------------------------
__global__ void k_zero_cnt() {
    int i = blockIdx.x * blockDim.x + threadIdx.x;
    if (i < Nn) g_cnt[i] = 0;
}

__global__ void k_hist(const int* __restrict__ dst) {
    int e = blockIdx.x * blockDim.x + threadIdx.x;
    if (e >= ETe) return;
    int d = (e < Ee) ? dst[e] : e - Ee;
    atomicAdd(&g_cnt[d], 1);
}

// single-block exclusive scan over g_cnt (50000 elems)
__global__ void k_scan() {
    __shared__ int sm[1024];
    int t = threadIdx.x;
    const int CH = (Nn + 1023) / 1024;   // 49
    int start = t * CH;
    int end = start + CH; if (end > Nn) end = Nn; if (start > Nn) start = Nn;
    int sum = 0;
    for (int i = start; i < end; i++) sum += g_cnt[i];
    sm[t] = sum;
    __syncthreads();
    for (int off = 1; off < 1024; off <<= 1) {
        int v = (t >= off) ? sm[t - off] : 0;
        __syncthreads();
        sm[t] += v;
        __syncthreads();
    }
    int excl = sm[t] - sum;
    for (int i = start; i < end; i++) {
        g_off[i] = excl; g_cur[i] = excl;
        excl += g_cnt[i];
    }
    if (t == 1023) g_off[Nn] = sm[1023];
}

__global__ void k_fill(const int* __restrict__ src, const int* __restrict__ dst) {
    int e = blockIdx.x * blockDim.x + threadIdx.x;
    if (e >= ETe) return;
    int s = (e < Ee) ? src[e] : e - Ee;
    int d = (e < Ee) ? dst[e] : e - Ee;
    int pos = atomicAdd(&g_cur[d], 1);
    g_csrc[pos] = s;
}

// ---------------- GEMM1: g_h1 = x @ W1  (N x 128 @ 128 x 128) --------------
__global__ void k_gemm1(const float* __restrict__ x, const float* __restrict__ W) {
    __shared__ float xs[32][33];
    __shared__ __align__(16) float Ws[32 * 128];

    int tid = threadIdx.x;        // 256 threads
    int ty = tid >> 5;
    int tx = tid & 31;
    int r0 = ty * 4, c0 = tx * 4;
    int rowBase = blockIdx.x * 32;

    float4 acc[4];
#pragma unroll
    for (int i = 0; i < 4; i++) acc[i] = make_float4(0.f, 0.f, 0.f, 0.f);

    int lr = tid >> 3;
    int lk = (tid & 7) * 4;

    for (int kk = 0; kk < FIN; kk += 32) {
        {
            int gr = rowBase + lr;
            float4 v = make_float4(0.f, 0.f, 0.f, 0.f);
            if (gr < Nn) v = *(const float4*)(x + (size_t)gr * FIN + kk + lk);
            xs[lr][lk + 0] = v.x; xs[lr][lk + 1] = v.y;
            xs[lr][lk + 2] = v.z; xs[lr][lk + 3] = v.w;
        }
#pragma unroll
        for (int it = 0; it < 4; it++) {
            int f = it * 1024 + tid * 4;
            *(float4*)&Ws[f] = *(const float4*)(W + kk * HD + f);
        }
        __syncthreads();
#pragma unroll
        for (int k = 0; k < 32; k++) {
            float4 b = *(float4*)&Ws[k * HD + c0];
#pragma unroll
            for (int i = 0; i < 4; i++) {
                float a = xs[r0 + i][k];
                acc[i].x += a * b.x; acc[i].y += a * b.y;
                acc[i].z += a * b.z; acc[i].w += a * b.w;
            }
        }
        __syncthreads();
    }
#pragma unroll
    for (int i = 0; i < 4; i++) {
        int gr = rowBase + r0 + i;
        if (gr < Nn) *(float4*)(g_h1 + (size_t)gr * HD + c0) = acc[i];
    }
}

// ---------------- per-node attention logits, layer 1 ------------------------
__global__ void k_attn1(const float* __restrict__ a_src, const float* __restrict__ a_dst) {
    __shared__ float s_as[NH * HID], s_ad[NH * HID];
    if (threadIdx.x < NH * HID) {
        s_as[threadIdx.x] = a_src[threadIdx.x];
        s_ad[threadIdx.x] = a_dst[threadIdx.x];
    }
    __syncthreads();
    int i = blockIdx.x * blockDim.x + threadIdx.x;
    if (i >= Nn * NH) return;
    int n = i >> 2, h = i & 3;
    const float* hp = g_h1 + (size_t)n * HD + h * HID;
    float ss = 0.f, sd = 0.f;
#pragma unroll
    for (int d = 0; d < HID; d++) {
        float v = hp[d];
        ss += v * s_as[h * HID + d];
        sd += v * s_ad[h * HID + d];
    }
    g_als1[i] = ss; g_ald1[i] = sd;
}

// ---------------- layer1 fused segment-softmax + aggregation (warp/dst) ----
__global__ void k_agg1() {
    int d = blockIdx.x * 8 + (threadIdx.x >> 5);
    int lane = threadIdx.x & 31;
    if (d >= Nn) return;
    int beg = g_off[d], end = g_off[d + 1];

    float4 ald = *(const float4*)(g_ald1 + d * NH);

    // pass 1: segment max (leaky-relu'd logits), per head
    float4 mx = make_float4(negInf(), negInf(), negInf(), negInf());
    for (int e = beg + lane; e < end; e += 32) {
        int s = g_csrc[e];
        float4 as = *(const float4*)(g_als1 + s * NH);
        mx.x = fmaxf(mx.x, leaky(as.x + ald.x));
        mx.y = fmaxf(mx.y, leaky(as.y + ald.y));
        mx.z = fmaxf(mx.z, leaky(as.z + ald.z));
        mx.w = fmaxf(mx.w, leaky(as.w + ald.w));
    }
#pragma unroll
    for (int o = 16; o; o >>= 1) {
        mx.x = fmaxf(mx.x, __shfl_xor_sync(0xffffffffu, mx.x, o));
        mx.y = fmaxf(mx.y, __shfl_xor_sync(0xffffffffu, mx.y, o));
        mx.z = fmaxf(mx.z, __shfl_xor_sync(0xffffffffu, mx.z, o));
        mx.w = fmaxf(mx.w, __shfl_xor_sync(0xffffffffu, mx.w, o));
    }

    // pass 2: exp-sum per head
    float4 den = make_float4(0.f, 0.f, 0.f, 0.f);
    for (int e = beg + lane; e < end; e += 32) {
        int s = g_csrc[e];
        float4 as = *(const float4*)(g_als1 + s * NH);
        den.x += __expf(leaky(as.x + ald.x) - mx.x);
        den.y += __expf(leaky(as.y + ald.y) - mx.y);
        den.z += __expf(leaky(as.z + ald.z) - mx.z);
        den.w += __expf(leaky(as.w + ald.w) - mx.w);
    }
#pragma unroll
    for (int o = 16; o; o >>= 1) {
        den.x += __shfl_xor_sync(0xffffffffu, den.x, o);
        den.y += __shfl_xor_sync(0xffffffffu, den.y, o);
        den.z += __shfl_xor_sync(0xffffffffu, den.z, o);
        den.w += __shfl_xor_sync(0xffffffffu, den.w, o);
    }

    // pass 3: weighted feature gather. lane owns cols [lane*4, lane*4+4);
    // head = lane>>3. Each lane recomputes alpha for its head.
    int head = lane >> 3;
    float aldh = sel4(ald, head);
    float mh   = sel4(mx, head);
    float invh = 1.f / sel4(den, head);
    float4 acc = make_float4(0.f, 0.f, 0.f, 0.f);
    for (int e = beg; e < end; e++) {
        int s = g_csrc[e];                       // broadcast
        float ash = __ldg(g_als1 + s * NH + head);
        float alpha = __expf(leaky(ash + aldh) - mh) * invh;
        float4 v = *(const float4*)(g_h1 + (size_t)s * HD + lane * 4);
        acc.x += v.x * alpha; acc.y += v.y * alpha;
        acc.z += v.z * alpha; acc.w += v.w * alpha;
    }
    *(float4*)(g_out1 + (size_t)d * HD + lane * 4) = acc;
}

// ---------------- GEMM2 (fused bias+elu on input) + layer2 logits ----------
__global__ void k_gemm2(const float* __restrict__ b1, const float* __restrict__ W2,
                        const float* __restrict__ as2, const float* __restrict__ ad2) {
    __shared__ float sW[HD * NCLS];
    __shared__ float sb[HD];
    __shared__ float sa[NCLS], sdv[NCLS];
    int t = threadIdx.x;   // 128 threads
    for (int i = t; i < HD * NCLS; i += 128) sW[i] = W2[i];
    sb[t] = b1[t];
    if (t < NCLS) { sa[t] = as2[t]; sdv[t] = ad2[t]; }
    __syncthreads();
    int n = blockIdx.x * 128 + t;
    if (n >= Nn) return;
    float acc[NCLS];
#pragma unroll
    for (int c = 0; c < NCLS; c++) acc[c] = 0.f;
    const float* xp = g_out1 + (size_t)n * HD;
    for (int k = 0; k < HD; k++) {
        float xv = xp[k] + sb[k];
        xv = xv > 0.f ? xv : expm1f(xv);          // elu
#pragma unroll
        for (int c = 0; c < NCLS; c++) acc[c] += xv * sW[k * NCLS + c];
    }
    float ss = 0.f, sd = 0.f;
#pragma unroll
    for (int c = 0; c < NCLS; c++) {
        g_h2[n * NCLS + c] = acc[c];
        ss += acc[c] * sa[c];
        sd += acc[c] * sdv[c];
    }
    g_als2[n] = ss; g_ald2[n] = sd;
}

// ---------------- layer2 fused segment-softmax + aggregation (warp/dst) ----
__global__ void k_agg2() {
    int d = blockIdx.x * 8 + (threadIdx.x >> 5);
    int lane = threadIdx.x & 31;
    if (d >= Nn) return;
    int beg = g_off[d], end = g_off[d + 1];

    float ald = g_ald2[d];

    float mxv = negInf();
    for (int e = beg + lane; e < end; e += 32) {
        int s = g_csrc[e];
        mxv = fmaxf(mxv, leaky(g_als2[s] + ald));
    }
#pragma unroll
    for (int o = 16; o; o >>= 1) mxv = fmaxf(mxv, __shfl_xor_sync(0xffffffffu, mxv, o));

    float den = 0.f;
    for (int e = beg + lane; e < end; e += 32) {
        int s = g_csrc[e];
        den += __expf(leaky(g_als2[s] + ald) - mxv);
    }
#pragma unroll
    for (int o = 16; o; o >>= 1) den += __shfl_xor_sync(0xffffffffu, den, o);
    float inv = 1.f / den;

    // pass 3: two edges per iteration. lanes 0-15 -> edge e (class lane),
    // lanes 16-31 -> edge e+1 (class lane-16).
    int half = lane >> 4;         // 0 or 1
    int cls  = lane & 15;
    float acc = 0.f;
    for (int e = beg; e < end; e += 2) {
        int idx = e + half;
        bool valid = idx < end;
        int s = valid ? g_csrc[idx] : 0;
        float alpha = __expf(leaky(g_als2[s] + ald) - mxv) * inv;
        float v = valid ? g_h2[s * NCLS + cls] * alpha : 0.f;
        acc += v;
    }
    acc += __shfl_xor_sync(0xffffffffu, acc, 16);
    if (half == 0) g_out2[d * NCLS + cls] = acc;
}

// ---------------- bias + log_softmax ----------------------------------------
__global__ void k_final(const float* __restrict__ b2, float* __restrict__ y) {
    __shared__ float sb[NCLS];
    if (threadIdx.x < NCLS) sb[threadIdx.x] = b2[threadIdx.x];
    __syncthreads();
    int n = blockIdx.x * blockDim.x + threadIdx.x;
    if (n >= Nn) return;
    float v[NCLS];
    float mx = negInf();
#pragma unroll
    for (int c = 0; c < NCLS; c++) {
        v[c] = g_out2[n * NCLS + c] + sb[c];
        mx = fmaxf(mx, v[c]);
    }
    float sm = 0.f;
#pragma unroll
    for (int c = 0; c < NCLS; c++) sm += __expf(v[c] - mx);
    float l = mx + logf(sm);
#pragma unroll
    for (int c = 0; c < NCLS; c++) y[n * NCLS + c] = v[c] - l;
}

// ---------------- launch -----------------------------------------------------
extern "C" void kernel_launch(void* const* d_in, const int* in_sizes, int n_in,
                              void* d_out, int out_size) {
    const float* x   = (const float*)d_in[0];
    const int*   ei  = (const int*)  d_in[1];
    const float* W1  = (const float*)d_in[2];
    const float* as1 = (const float*)d_in[3];
    const float* ad1 = (const float*)d_in[4];
    const float* b1  = (const float*)d_in[5];
    const float* W2  = (const float*)d_in[6];
    const float* as2 = (const float*)d_in[7];
    const float* ad2 = (const float*)d_in[8];
    const float* b2  = (const float*)d_in[9];
    float* out = (float*)d_out;

    const int* srcp = ei;
    const int* dstp = ei + Ee;

    int eb = (ETe + 255) / 256;

    // CSR build
    k_zero_cnt<<<(Nn + 255) / 256, 256>>>();
    k_hist<<<eb, 256>>>(dstp);
    k_scan<<<1, 1024>>>();
    k_fill<<<eb, 256>>>(srcp, dstp);

    // dense layer 1
    k_gemm1<<<(Nn + 31) / 32, 256>>>(x, W1);
    k_attn1<<<(Nn * NH + 255) / 256, 256>>>(as1, ad1);

    // fused layer-1 softmax + aggregation
    k_agg1<<<(Nn + 7) / 8, 256>>>();

    // dense layer 2
    k_gemm2<<<(Nn + 127) / 128, 128>>>(b1, W2, as2, ad2);

    // fused layer-2 softmax + aggregation
    k_agg2<<<(Nn + 7) / 8, 256>>>();

    k_final<<<(Nn + 255) / 256, 256>>>(b2, out);
}